// round 14
// baseline (speedup 1.0000x reference)
#include <cuda_runtime.h>
#include <cuda_fp16.h>
#include <cstdint>

#define NUM_T 8192
#define DIM   1024
#define NEXP  8
#define DFFN  2048
#define OUT_MAT (NUM_T * DIM)

#define BM 128
#define BN 256
#define BKH 64                          // K elements (halfs) per stage
#define SA_STRIDE 72                    // halfs, conflict-free ldmatrix
#define SA_SZ (BM * SA_STRIDE)          // 9216 halfs = 18 KB
#define SB_SZ 16384                     // halfs = 32 KB (two frag tiles)
#define SMEM_G (2 * (SA_SZ + SB_SZ) * 2)   // 102400 B (2 stages)

// ---------------- scratch (device globals; no allocations allowed) ----------------
__device__ __half g_Xh [NUM_T * DIM];             // 16 MB fp16 x (row-major)
__device__ __half g_W1h[DIM * NEXP * DFFN];       // 32 MB fp16 w1 (row-major)
__device__ __half g_W2B[NEXP * 8 * 32 * 8192];    // 32 MB w2 fragment tiles (GEMM1 B)
__device__ __half g_MB [NEXP * 8 * 16 * 8192];    // 16 MB M fragment tiles (GEMM2 B)
__device__ int    g_list[NEXP * NUM_T];
__device__ float  g_wsel[NEXP * NUM_T];
__device__ int    g_count[NEXP];
__device__ float  g_psum[NEXP];
__device__ float  g_zsum;

// ---------------- small helpers ----------------
__device__ __forceinline__ unsigned cvta_s(const void* p) {
    return (unsigned)__cvta_generic_to_shared((void*)p);
}
__device__ __forceinline__ void cpa16(void* sdst, const void* gsrc) {
    asm volatile("cp.async.cg.shared.global [%0], [%1], 16;"
                 :: "r"(cvta_s(sdst)), "l"(gsrc));
}
__device__ __forceinline__ void cpa_commit() {
    asm volatile("cp.async.commit_group;");
}
template<int N> __device__ __forceinline__ void cpa_wait() {
    asm volatile("cp.async.wait_group %0;" :: "n"(N));
}
__device__ __forceinline__ void ldsm4(uint32_t* a, const void* p) {
    asm volatile("ldmatrix.sync.aligned.m8n8.x4.shared.b16 {%0,%1,%2,%3}, [%4];"
                 : "=r"(a[0]), "=r"(a[1]), "=r"(a[2]), "=r"(a[3])
                 : "r"(cvta_s(p)));
}
__device__ __forceinline__ void mma16(float* c, const uint32_t* a, const uint32_t* b) {
    asm volatile("mma.sync.aligned.m16n8k16.row.col.f32.f16.f16.f32 "
                 "{%0,%1,%2,%3}, {%4,%5,%6,%7}, {%8,%9}, {%0,%1,%2,%3};"
                 : "+f"(c[0]), "+f"(c[1]), "+f"(c[2]), "+f"(c[3])
                 : "r"(a[0]), "r"(a[1]), "r"(a[2]), "r"(a[3]),
                   "r"(b[0]), "r"(b[1]));
}
__device__ __forceinline__ void red2(float* p, float a, float b) {
    asm volatile("red.global.v2.f32.add [%0], {%1, %2};"
                 :: "l"(p), "f"(a), "f"(b) : "memory");
}

// ---------------- kernel 1: fp16-round x and w1; block 0 zeroes accumulators ---------
__global__ void convert_kernel(const float4* __restrict__ x,
                               const float4* __restrict__ w1) {
    if (blockIdx.x == 0 && threadIdx.x < 32) {
        int t = threadIdx.x;
        if (t < NEXP) { g_count[t] = 0; g_psum[t] = 0.f; }
        if (t == 0)   { g_zsum = 0.f; }
    }
    const unsigned NX = (NUM_T * DIM) / 4;          // 2097152
    unsigned i = blockIdx.x * 256u + threadIdx.x;   // total NX + NW1 = 6291456
    float4 v; __half* dst;
    if (i < NX) { v = x[i];       dst = g_Xh  + (size_t)i * 4; }
    else        { v = w1[i - NX]; dst = g_W1h + (size_t)(i - NX) * 4; }
    __half2 h0 = __floats2half2_rn(v.x, v.y);
    __half2 h1 = __floats2half2_rn(v.z, v.w);
    uint2 o;
    o.x = *(uint32_t*)&h0;
    o.y = *(uint32_t*)&h1;
    *(uint2*)dst = o;
}

// ---------------- fragment packer for w2 (smem-staged, coalesced) --------------------
__global__ __launch_bounds__(256) void frag_pack_w2(const float* __restrict__ w2src) {
    __shared__ __half sh[64][136];      // padded: row stride 272 B
    constexpr int KT = DFFN / 64;
    int b  = blockIdx.x;
    int kt = b % KT;
    int nt = (b / KT) & 7;
    int e  = b / (KT * 8);
    int tid = threadIdx.x, lane = tid & 31, slot = tid >> 5;

    const float* se = w2src + (size_t)e * DFFN * DIM + (size_t)(kt * 64) * DIM
                    + nt * 128;
#pragma unroll
    for (int i = tid; i < 2048; i += 256) {      // 2048 float4
        int r = i >> 5, c4 = i & 31;
        float4 v = *(const float4*)(se + (size_t)r * DIM + c4 * 4);
        __half2 h0 = __floats2half2_rn(v.x, v.y);
        __half2 h1 = __floats2half2_rn(v.z, v.w);
        uint2 o; o.x = *(uint32_t*)&h0; o.y = *(uint32_t*)&h1;
        *(uint2*)&sh[r][c4 * 4] = o;
    }
    __syncthreads();

    __half* tile = g_W2B + (size_t)b * 8192;
#pragma unroll
    for (int j = 0; j < 4; j++) {
        int idx = slot * 4 + j;           // 0..31 -> (ks, tp)
        int ks = idx >> 3, tp = idx & 7;
        int kb = ks * 16 + 2 * (lane & 3);
        int n  = tp * 16 + (lane >> 2);
        __half h[8];
        h[0] = sh[kb][n];     h[1] = sh[kb + 1][n];
        h[2] = sh[kb + 8][n]; h[3] = sh[kb + 9][n];
        h[4] = sh[kb][n + 8];     h[5] = sh[kb + 1][n + 8];
        h[6] = sh[kb + 8][n + 8]; h[7] = sh[kb + 9][n + 8];
        *(uint4*)(tile + ks * 2048 + tp * 256 + lane * 8) = *(uint4*)h;
    }
}

// ---------------- router: 2 tokens per warp, 512 blocks; also zeroes out matrix ------
__global__ __launch_bounds__(256) void router_kernel(const float* __restrict__ x,
                                                     const float* __restrict__ wr,
                                                     float* __restrict__ out) {
    __shared__ float swr[NEXP][DIM];
    __shared__ float s_p[NEXP];
    __shared__ float s_z;

    int tid = threadIdx.x;

    {
        float4 z4 = make_float4(0.f, 0.f, 0.f, 0.f);
        float4* ob = (float4*)out + (size_t)blockIdx.x * 4096;
#pragma unroll
        for (int i = tid; i < 4096; i += 256) ob[i] = z4;
    }

    for (int i = tid; i < NEXP * DIM; i += 256) {
        int d = i >> 3, e = i & 7;
        swr[e][d] = wr[i];
    }
    if (tid < NEXP) s_p[tid] = 0.f;
    if (tid == 0)   s_z = 0.f;
    __syncthreads();

    int lane = tid & 31, warp = tid >> 5;
    int t0 = blockIdx.x * 16 + warp * 2;            // 2 tokens per warp

    float acc[2][NEXP];
#pragma unroll
    for (int tt = 0; tt < 2; tt++)
#pragma unroll
        for (int e = 0; e < NEXP; e++) acc[tt][e] = 0.f;

    const float4* xr0 = (const float4*)(x + (size_t)t0 * DIM);
    const float4* xr1 = (const float4*)(x + (size_t)(t0 + 1) * DIM);

    for (int c = lane; c < DIM / 4; c += 32) {
        float4 xv0 = xr0[c], xv1 = xr1[c];
#pragma unroll
        for (int e = 0; e < NEXP; e++) {
            float4 wv = *(const float4*)&swr[e][c * 4];
            acc[0][e] += xv0.x * wv.x + xv0.y * wv.y + xv0.z * wv.z + xv0.w * wv.w;
            acc[1][e] += xv1.x * wv.x + xv1.y * wv.y + xv1.z * wv.z + xv1.w * wv.w;
        }
    }
#pragma unroll
    for (int tt = 0; tt < 2; tt++)
#pragma unroll
        for (int e = 0; e < NEXP; e++)
            for (int o = 16; o; o >>= 1)
                acc[tt][e] += __shfl_xor_sync(0xffffffffu, acc[tt][e], o);

    if (lane < 2) {
        int t = t0 + lane;
        float m = acc[lane][0];
#pragma unroll
        for (int e = 1; e < NEXP; e++) m = fmaxf(m, acc[lane][e]);
        float p[NEXP], se = 0.f;
#pragma unroll
        for (int e = 0; e < NEXP; e++) { p[e] = expf(acc[lane][e] - m); se += p[e]; }
        float inv = 1.f / se;
#pragma unroll
        for (int e = 0; e < NEXP; e++) p[e] *= inv;
        float lse = m + logf(se);

        int e0 = 0;
#pragma unroll
        for (int e = 1; e < NEXP; e++) if (p[e] > p[e0]) e0 = e;
        int e1 = (e0 == 0) ? 1 : 0;
#pragma unroll
        for (int e = 0; e < NEXP; e++) if (e != e0 && p[e] > p[e1]) e1 = e;

        float w0 = p[e0], w1v = p[e1], s = w0 + w1v;
        w0 /= s; w1v /= s;

        int pos = atomicAdd(&g_count[e0], 1);
        g_list[e0 * NUM_T + pos] = t;  g_wsel[e0 * NUM_T + pos] = w0;
        pos = atomicAdd(&g_count[e1], 1);
        g_list[e1 * NUM_T + pos] = t;  g_wsel[e1 * NUM_T + pos] = w1v;

        atomicAdd(&s_z, lse * lse);
#pragma unroll
        for (int e = 0; e < NEXP; e++) atomicAdd(&s_p[e], p[e]);
    }
    __syncthreads();
    if (tid < NEXP) atomicAdd(&g_psum[tid], s_p[tid]);
    if (tid == 0)   atomicAdd(&g_zsum, s_z);
}

// ---------------- aux-loss outputs ----------------
__global__ void finalize_kernel(float* out_tail) {
    if (threadIdx.x == 0) {
        float z = g_zsum / (float)NUM_T;
        float lb = 0.f;
#pragma unroll
        for (int e = 0; e < NEXP; e++) {
            float f = (float)g_count[e] / (float)(NUM_T * 2);
            lb += f * (g_psum[e] / (float)NUM_T);
        }
        lb *= (float)NEXP;
        out_tail[0] = z;
        out_tail[1] = lb;
#pragma unroll
        for (int e = 0; e < NEXP; e++)
            out_tail[2 + e] = (float)g_count[e] / (float)(NUM_T * 2);
    }
}

// ================== 128x256 CTA tile, 8 warps x (64x64), 2-stage pipeline =============
// warp map: wm = (warp&1)*64 (2 m-bands), wnq = warp>>2? no: wnq = warp>>1 (4 n-groups)

// ---------------- GEMM1: M_e = W1_e @ W2_e; epilogue emits g_MB fragment tiles -------
__global__ __launch_bounds__(256) void moe_gemm1() {
    constexpr int ITERS = DFFN / BKH;       // 32
    const int e  = blockIdx.z;
    const int m0 = blockIdx.x * BM;

    extern __shared__ __half smem[];
    __half* sA = smem;                       // 2 stages x SA_SZ
    __half* sB = smem + 2 * SA_SZ;           // 2 stages x SB_SZ

    const int tid = threadIdx.x, lane = tid & 31, warp = tid >> 5;

    const __half* aptr[4];
#pragma unroll
    for (int i = 0; i < 4; i++) {
        int rr = m0 + (tid >> 3) + i * 32;
        aptr[i] = g_W1h + (size_t)rr * (NEXP * DFFN) + (size_t)e * DFFN
                + (tid & 7) * 8;
    }
    const __half* Bt0 = g_W2B + (size_t)((e * 8 + blockIdx.y * 2) * ITERS) * 8192;
    const __half* Bt1 = Bt0 + (size_t)ITERS * 8192;

    auto load_stage = [&](int it, int s) {
        __half* sAs = sA + s * SA_SZ;
        __half* sBs = sB + s * SB_SZ;
        int k0 = it * BKH;
#pragma unroll
        for (int i = 0; i < 4; i++)
            cpa16(sAs + ((tid >> 3) + i * 32) * SA_STRIDE + (tid & 7) * 8,
                  aptr[i] + k0);
        const __half* b0 = Bt0 + (size_t)it * 8192;
        const __half* b1 = Bt1 + (size_t)it * 8192;
#pragma unroll
        for (int p = 0; p < 4; p++) {
            cpa16(sBs + p * 2048 + tid * 8,        b0 + p * 2048 + tid * 8);
            cpa16(sBs + 8192 + p * 2048 + tid * 8, b1 + p * 2048 + tid * 8);
        }
        cpa_commit();
    };

    float acc[4][8][4];
#pragma unroll
    for (int a = 0; a < 4; a++)
#pragma unroll
        for (int b = 0; b < 8; b++)
#pragma unroll
            for (int c = 0; c < 4; c++) acc[a][b][c] = 0.f;

    const int wm  = (warp & 1) * 64;
    const int wnq = warp >> 1;               // 0..3, n offset wnq*64

    auto compute_stage = [&](int s) {
        const __half* sAs = sA + s * SA_SZ;
        const __half* sBs = sB + s * SB_SZ;
#pragma unroll
        for (int ks = 0; ks < 4; ks++) {
            uint32_t afr[4][4];
#pragma unroll
            for (int tm = 0; tm < 4; tm++) {
                const __half* p = sAs + (wm + tm * 16 + (lane & 15)) * SA_STRIDE
                                + ks * 16 + (lane >> 4) * 8;
                ldsm4(afr[tm], p);
            }
            uint4 bfr[4];
            const __half* bq = sBs + (wnq >> 1) * 8192 + ks * 2048
                             + (wnq & 1) * 1024 + lane * 8;
#pragma unroll
            for (int tp = 0; tp < 4; tp++)
                bfr[tp] = *(const uint4*)(bq + tp * 256);
#pragma unroll
            for (int tm = 0; tm < 4; tm++)
#pragma unroll
                for (int tn = 0; tn < 8; tn++) {
                    const uint32_t* bb = (tn & 1) ? &bfr[tn >> 1].z : &bfr[tn >> 1].x;
                    mma16(acc[tm][tn], afr[tm], bb);
                }
        }
    };

    load_stage(0, 0);
    load_stage(1, 1);
    cpa_wait<1>();
    __syncthreads();
#pragma unroll 1
    for (int it = 0; it < ITERS; ++it) {
        compute_stage(it & 1);
        __syncthreads();
        if (it + 2 < ITERS) {
            load_stage(it + 2, it & 1);
            cpa_wait<1>();
            __syncthreads();
        } else if (it + 1 < ITERS) {
            cpa_wait<0>();
            __syncthreads();
        }
    }

    // ---- epilogue: restage 128x256 C through smem (stride 264), emit 2x2 frag tiles --
    __syncthreads();
    __half* sh = smem;                     // [128][264] halfs = 67584 B
    const int wn = wnq * 64;
#pragma unroll
    for (int tm = 0; tm < 4; tm++)
#pragma unroll
        for (int half = 0; half < 2; half++) {
            int r = wm + tm * 16 + (lane >> 2) + half * 8;
#pragma unroll
            for (int tn = 0; tn < 8; tn++) {
                int c = wn + tn * 8 + (lane & 3) * 2;
                __half2 h = __floats2half2_rn(acc[tm][tn][half * 2 + 0],
                                              acc[tm][tn][half * 2 + 1]);
                *(__half2*)(sh + r * 264 + c) = h;
            }
        }
    __syncthreads();
#pragma unroll
    for (int nsub = 0; nsub < 2; nsub++) {
        int nt = blockIdx.y * 2 + nsub;
#pragma unroll
        for (int sub = 0; sub < 2; sub++) {
            int kt = blockIdx.x * 2 + sub;      // GEMM2 K-tile index (KT=16)
            __half* tile = g_MB + ((size_t)(e * 8 + nt) * 16 + kt) * 8192;
#pragma unroll
            for (int j = 0; j < 4; j++) {
                int idx = warp * 4 + j;         // (ks, tp)
                int ks = idx >> 3, tp = idx & 7;
                int kb = sub * 64 + ks * 16 + 2 * (lane & 3);
                int n  = nsub * 128 + tp * 16 + (lane >> 2);
                __half h[8];
                h[0] = sh[kb * 264 + n];       h[1] = sh[(kb + 1) * 264 + n];
                h[2] = sh[(kb + 8) * 264 + n]; h[3] = sh[(kb + 9) * 264 + n];
                h[4] = sh[kb * 264 + n + 8];       h[5] = sh[(kb + 1) * 264 + n + 8];
                h[6] = sh[(kb + 8) * 264 + n + 8]; h[7] = sh[(kb + 9) * 264 + n + 8];
                *(uint4*)(tile + ks * 2048 + tp * 256 + lane * 8) = *(uint4*)h;
            }
        }
    }
}

// ---------------- GEMM2: out[tok] += wsel * (gather(x) @ M_e) ------------------------
__global__ __launch_bounds__(256) void moe_gemm2(float* out) {
    constexpr int ITERS = DIM / BKH;        // 16
    const int e   = blockIdx.z;
    const int cnt = g_count[e];
    const int m0  = blockIdx.x * BM;
    if (m0 >= cnt) return;
    const int n0  = blockIdx.y * BN;

    extern __shared__ __half smem[];
    __half* sA = smem;
    __half* sB = smem + 2 * SA_SZ;

    const int tid = threadIdx.x, lane = tid & 31, warp = tid >> 5;

    const __half* aptr[4];
#pragma unroll
    for (int i = 0; i < 4; i++) {
        int rr = m0 + (tid >> 3) + i * 32;
        if (rr >= cnt) rr = cnt - 1;
        int tok = g_list[e * NUM_T + rr];
        aptr[i] = g_Xh + (size_t)tok * DIM + (tid & 7) * 8;
    }
    const __half* Bt0 = g_MB + (size_t)((e * 8 + blockIdx.y * 2) * ITERS) * 8192;
    const __half* Bt1 = Bt0 + (size_t)ITERS * 8192;

    auto load_stage = [&](int it, int s) {
        __half* sAs = sA + s * SA_SZ;
        __half* sBs = sB + s * SB_SZ;
        int k0 = it * BKH;
#pragma unroll
        for (int i = 0; i < 4; i++)
            cpa16(sAs + ((tid >> 3) + i * 32) * SA_STRIDE + (tid & 7) * 8,
                  aptr[i] + k0);
        const __half* b0 = Bt0 + (size_t)it * 8192;
        const __half* b1 = Bt1 + (size_t)it * 8192;
#pragma unroll
        for (int p = 0; p < 4; p++) {
            cpa16(sBs + p * 2048 + tid * 8,        b0 + p * 2048 + tid * 8);
            cpa16(sBs + 8192 + p * 2048 + tid * 8, b1 + p * 2048 + tid * 8);
        }
        cpa_commit();
    };

    float acc[4][8][4];
#pragma unroll
    for (int a = 0; a < 4; a++)
#pragma unroll
        for (int b = 0; b < 8; b++)
#pragma unroll
            for (int c = 0; c < 4; c++) acc[a][b][c] = 0.f;

    const int wm  = (warp & 1) * 64;
    const int wnq = warp >> 1;

    auto compute_stage = [&](int s) {
        const __half* sAs = sA + s * SA_SZ;
        const __half* sBs = sB + s * SB_SZ;
#pragma unroll
        for (int ks = 0; ks < 4; ks++) {
            uint32_t afr[4][4];
#pragma unroll
            for (int tm = 0; tm < 4; tm++) {
                const __half* p = sAs + (wm + tm * 16 + (lane & 15)) * SA_STRIDE
                                + ks * 16 + (lane >> 4) * 8;
                ldsm4(afr[tm], p);
            }
            uint4 bfr[4];
            const __half* bq = sBs + (wnq >> 1) * 8192 + ks * 2048
                             + (wnq & 1) * 1024 + lane * 8;
#pragma unroll
            for (int tp = 0; tp < 4; tp++)
                bfr[tp] = *(const uint4*)(bq + tp * 256);
#pragma unroll
            for (int tm = 0; tm < 4; tm++)
#pragma unroll
                for (int tn = 0; tn < 8; tn++) {
                    const uint32_t* bb = (tn & 1) ? &bfr[tn >> 1].z : &bfr[tn >> 1].x;
                    mma16(acc[tm][tn], afr[tm], bb);
                }
        }
    };

    load_stage(0, 0);
    load_stage(1, 1);
    cpa_wait<1>();
    __syncthreads();
#pragma unroll 1
    for (int it = 0; it < ITERS; ++it) {
        compute_stage(it & 1);
        __syncthreads();
        if (it + 2 < ITERS) {
            load_stage(it + 2, it & 1);
            cpa_wait<1>();
            __syncthreads();
        } else if (it + 1 < ITERS) {
            cpa_wait<0>();
            __syncthreads();
        }
    }

    // ---- epilogue: weighted vector reduction into out ----
    const int wn = wnq * 64;
#pragma unroll
    for (int tm = 0; tm < 4; tm++) {
#pragma unroll
        for (int half = 0; half < 2; half++) {
            int r  = wm + tm * 16 + (lane >> 2) + half * 8;
            int gr = m0 + r;
            if (gr < cnt) {
                float w   = g_wsel[e * NUM_T + gr];
                int   tok = g_list[e * NUM_T + gr];
                float* orow = out + (size_t)tok * DIM + n0 + wn;
#pragma unroll
                for (int tn = 0; tn < 8; tn++) {
                    int c = tn * 8 + (lane & 3) * 2;
                    red2(orow + c,
                         w * acc[tm][tn][half * 2 + 0],
                         w * acc[tm][tn][half * 2 + 1]);
                }
            }
        }
    }
}

// ---------------- launch ----------------
extern "C" void kernel_launch(void* const* d_in, const int* in_sizes, int n_in,
                              void* d_out, int out_size) {
    const float* x  = (const float*)d_in[0];
    const float* wr = (const float*)d_in[1];
    const float* w1 = (const float*)d_in[2];
    const float* w2 = (const float*)d_in[3];
    float* out = (float*)d_out;

    cudaFuncSetAttribute(moe_gemm1,
                         cudaFuncAttributeMaxDynamicSharedMemorySize, SMEM_G);
    cudaFuncSetAttribute(moe_gemm2,
                         cudaFuncAttributeMaxDynamicSharedMemorySize, SMEM_G);

    // kernel order: convert(1), frag(2), router(3), gemm1(4 <- ncu), gemm2(5), fin(6)
    convert_kernel<<<24576, 256>>>((const float4*)x, (const float4*)w1);
    frag_pack_w2<<<NEXP * 8 * (DFFN / 64), 256>>>(w2);
    router_kernel<<<NUM_T / 16, 256>>>(x, wr, out);
    moe_gemm1<<<dim3(DIM / BM, DIM / BN, NEXP), 256, SMEM_G>>>();
    moe_gemm2<<<dim3(NUM_T / BM, DIM / BN, NEXP), 256, SMEM_G>>>(out);
    finalize_kernel<<<1, 32>>>(out + OUT_MAT);
}

// round 15
// speedup vs baseline: 1.1549x; 1.1549x over previous
#include <cuda_runtime.h>
#include <cuda_fp16.h>
#include <cstdint>

#define NUM_T 8192
#define DIM   1024
#define NEXP  8
#define DFFN  2048
#define OUT_MAT (NUM_T * DIM)

#define BM 128
#define BN 128
#define BKH 64                          // K elements (halfs) per stage
#define SA_STRIDE 72                    // halfs, conflict-free ldmatrix
#define SA_SZ (BM * SA_STRIDE)          // 9216 halfs = 18 KB
#define SB_SZ 8192                      // halfs = 16 KB (frag tile)
#define SMEM1_BYTES (3 * (SA_SZ + SB_SZ) * 2)   // 104448 B (GEMM1: 3 stages)
#define SMEM2_BYTES (2 * (SA_SZ + SB_SZ) * 2)   //  69632 B (GEMM2: 2 stages)

#define RT_BLOCKS 512                   // router blocks (scheduled first)
#define CV_BLOCKS 24576                 // convert blocks

// ---------------- scratch (device globals; zero-initialized; no allocs) -------------
__device__ __half g_Xh [NUM_T * DIM];             // 16 MB fp16 x (row-major)
__device__ __half g_W1h[DIM * NEXP * DFFN];       // 32 MB fp16 w1 (row-major)
__device__ __half g_W2B[NEXP * 8 * 32 * 8192];    // 32 MB w2 fragment tiles (GEMM1 B)
__device__ __half g_MB [NEXP * 8 * 16 * 8192];    // 16 MB M fragment tiles (GEMM2 B)
__device__ int    g_list[NEXP * NUM_T];
__device__ float  g_wsel[NEXP * NUM_T];
__device__ int    g_count[NEXP];                  // zero-init; finalize re-zeroes
__device__ float  g_psum[NEXP];                   // zero-init; finalize re-zeroes
__device__ float  g_zsum;                         // zero-init; finalize re-zeroes

// ---------------- small helpers ----------------
__device__ __forceinline__ unsigned cvta_s(const void* p) {
    return (unsigned)__cvta_generic_to_shared((void*)p);
}
__device__ __forceinline__ void cpa16(void* sdst, const void* gsrc) {
    asm volatile("cp.async.cg.shared.global [%0], [%1], 16;"
                 :: "r"(cvta_s(sdst)), "l"(gsrc));
}
__device__ __forceinline__ void cpa_commit() {
    asm volatile("cp.async.commit_group;");
}
template<int N> __device__ __forceinline__ void cpa_wait() {
    asm volatile("cp.async.wait_group %0;" :: "n"(N));
}
__device__ __forceinline__ void ldsm4(uint32_t* a, const void* p) {
    asm volatile("ldmatrix.sync.aligned.m8n8.x4.shared.b16 {%0,%1,%2,%3}, [%4];"
                 : "=r"(a[0]), "=r"(a[1]), "=r"(a[2]), "=r"(a[3])
                 : "r"(cvta_s(p)));
}
__device__ __forceinline__ void mma16(float* c, const uint32_t* a, const uint32_t* b) {
    asm volatile("mma.sync.aligned.m16n8k16.row.col.f32.f16.f16.f32 "
                 "{%0,%1,%2,%3}, {%4,%5,%6,%7}, {%8,%9}, {%0,%1,%2,%3};"
                 : "+f"(c[0]), "+f"(c[1]), "+f"(c[2]), "+f"(c[3])
                 : "r"(a[0]), "r"(a[1]), "r"(a[2]), "r"(a[3]),
                   "r"(b[0]), "r"(b[1]));
}
__device__ __forceinline__ void red2(float* p, float a, float b) {
    asm volatile("red.global.v2.f32.add [%0], {%1, %2};"
                 :: "l"(p), "f"(a), "f"(b) : "memory");
}

// ---------------- fused front kernel: router (blocks 0..511) + convert (rest) -------
// Router blocks enter wave 1 and overlap with the bandwidth-bound convert blocks.
__global__ __launch_bounds__(256) void front_kernel(
        const float4* __restrict__ x4, const float4* __restrict__ w14,
        const float*  __restrict__ x,  const float*  __restrict__ wr,
        float* __restrict__ out) {
    __shared__ float swr[NEXP][DIM];
    __shared__ float s_p[NEXP];
    __shared__ float s_z;

    int tid = threadIdx.x;

    if (blockIdx.x >= RT_BLOCKS) {
        // ---- convert path: fp16-round x and w1 into scratch ----
        const unsigned NX = (NUM_T * DIM) / 4;          // 2097152
        unsigned i = (blockIdx.x - RT_BLOCKS) * 256u + tid;
        float4 v; __half* dst;
        if (i < NX) { v = x4[i];       dst = g_Xh  + (size_t)i * 4; }
        else        { v = w14[i - NX]; dst = g_W1h + (size_t)(i - NX) * 4; }
        __half2 h0 = __floats2half2_rn(v.x, v.y);
        __half2 h1 = __floats2half2_rn(v.z, v.w);
        uint2 o;
        o.x = *(uint32_t*)&h0;
        o.y = *(uint32_t*)&h1;
        *(uint2*)dst = o;
        return;
    }

    // ---- router path (2 tokens per warp); also zeroes this block's out slice ----
    int rblk = blockIdx.x;                              // 0..511
    {
        float4 z4 = make_float4(0.f, 0.f, 0.f, 0.f);
        float4* ob = (float4*)out + (size_t)rblk * 4096;
#pragma unroll
        for (int i = tid; i < 4096; i += 256) ob[i] = z4;
    }

    for (int i = tid; i < NEXP * DIM; i += 256) {
        int d = i >> 3, e = i & 7;
        swr[e][d] = wr[i];
    }
    if (tid < NEXP) s_p[tid] = 0.f;
    if (tid == 0)   s_z = 0.f;
    __syncthreads();

    int lane = tid & 31, warp = tid >> 5;
    int t0 = rblk * 16 + warp * 2;                      // 2 tokens per warp

    float acc[2][NEXP];
#pragma unroll
    for (int tt = 0; tt < 2; tt++)
#pragma unroll
        for (int e = 0; e < NEXP; e++) acc[tt][e] = 0.f;

    const float4* xr0 = (const float4*)(x + (size_t)t0 * DIM);
    const float4* xr1 = (const float4*)(x + (size_t)(t0 + 1) * DIM);

    for (int c = lane; c < DIM / 4; c += 32) {
        float4 xv0 = xr0[c], xv1 = xr1[c];
#pragma unroll
        for (int e = 0; e < NEXP; e++) {
            float4 wv = *(const float4*)&swr[e][c * 4];
            acc[0][e] += xv0.x * wv.x + xv0.y * wv.y + xv0.z * wv.z + xv0.w * wv.w;
            acc[1][e] += xv1.x * wv.x + xv1.y * wv.y + xv1.z * wv.z + xv1.w * wv.w;
        }
    }
#pragma unroll
    for (int tt = 0; tt < 2; tt++)
#pragma unroll
        for (int e = 0; e < NEXP; e++)
            for (int o = 16; o; o >>= 1)
                acc[tt][e] += __shfl_xor_sync(0xffffffffu, acc[tt][e], o);

    if (lane < 2) {                                     // lane tt owns token t0+tt
        int t = t0 + lane;
        float m = acc[lane][0];
#pragma unroll
        for (int e = 1; e < NEXP; e++) m = fmaxf(m, acc[lane][e]);
        float p[NEXP], se = 0.f;
#pragma unroll
        for (int e = 0; e < NEXP; e++) { p[e] = expf(acc[lane][e] - m); se += p[e]; }
        float inv = 1.f / se;
#pragma unroll
        for (int e = 0; e < NEXP; e++) p[e] *= inv;
        float lse = m + logf(se);

        int e0 = 0;
#pragma unroll
        for (int e = 1; e < NEXP; e++) if (p[e] > p[e0]) e0 = e;
        int e1 = (e0 == 0) ? 1 : 0;
#pragma unroll
        for (int e = 0; e < NEXP; e++) if (e != e0 && p[e] > p[e1]) e1 = e;

        float w0 = p[e0], w1v = p[e1], s = w0 + w1v;
        w0 /= s; w1v /= s;

        int pos = atomicAdd(&g_count[e0], 1);
        g_list[e0 * NUM_T + pos] = t;  g_wsel[e0 * NUM_T + pos] = w0;
        pos = atomicAdd(&g_count[e1], 1);
        g_list[e1 * NUM_T + pos] = t;  g_wsel[e1 * NUM_T + pos] = w1v;

        atomicAdd(&s_z, lse * lse);
#pragma unroll
        for (int e = 0; e < NEXP; e++) atomicAdd(&s_p[e], p[e]);
    }
    __syncthreads();
    if (tid < NEXP) atomicAdd(&g_psum[tid], s_p[tid]);
    if (tid == 0)   atomicAdd(&g_zsum, s_z);
}

// ---------------- fragment packer for w2 (smem-staged, coalesced) --------------------
__global__ __launch_bounds__(256) void frag_pack_w2(const float* __restrict__ w2src) {
    __shared__ __half sh[64][136];      // padded: row stride 272 B
    constexpr int KT = DFFN / 64;
    int b  = blockIdx.x;
    int kt = b % KT;
    int nt = (b / KT) & 7;
    int e  = b / (KT * 8);
    int tid = threadIdx.x, lane = tid & 31, slot = tid >> 5;

    const float* se = w2src + (size_t)e * DFFN * DIM + (size_t)(kt * 64) * DIM
                    + nt * 128;
#pragma unroll
    for (int i = tid; i < 2048; i += 256) {      // 2048 float4
        int r = i >> 5, c4 = i & 31;
        float4 v = *(const float4*)(se + (size_t)r * DIM + c4 * 4);
        __half2 h0 = __floats2half2_rn(v.x, v.y);
        __half2 h1 = __floats2half2_rn(v.z, v.w);
        uint2 o; o.x = *(uint32_t*)&h0; o.y = *(uint32_t*)&h1;
        *(uint2*)&sh[r][c4 * 4] = o;
    }
    __syncthreads();

    __half* tile = g_W2B + (size_t)b * 8192;
#pragma unroll
    for (int j = 0; j < 4; j++) {
        int idx = slot * 4 + j;           // 0..31 -> (ks, tp)
        int ks = idx >> 3, tp = idx & 7;
        int kb = ks * 16 + 2 * (lane & 3);
        int n  = tp * 16 + (lane >> 2);
        __half h[8];
        h[0] = sh[kb][n];     h[1] = sh[kb + 1][n];
        h[2] = sh[kb + 8][n]; h[3] = sh[kb + 9][n];
        h[4] = sh[kb][n + 8];     h[5] = sh[kb + 1][n + 8];
        h[6] = sh[kb + 8][n + 8]; h[7] = sh[kb + 9][n + 8];
        *(uint4*)(tile + ks * 2048 + tp * 256 + lane * 8) = *(uint4*)h;
    }
}

// ---------------- aux-loss outputs + state reset for next replay ----------------
__global__ void finalize_kernel(float* out_tail) {
    if (threadIdx.x == 0) {
        float z = g_zsum / (float)NUM_T;
        float lb = 0.f;
#pragma unroll
        for (int e = 0; e < NEXP; e++) {
            float f = (float)g_count[e] / (float)(NUM_T * 2);
            lb += f * (g_psum[e] / (float)NUM_T);
        }
        lb *= (float)NEXP;
        out_tail[0] = z;
        out_tail[1] = lb;
#pragma unroll
        for (int e = 0; e < NEXP; e++)
            out_tail[2 + e] = (float)g_count[e] / (float)(NUM_T * 2);
        // reset accumulators so the next graph replay starts from zero
#pragma unroll
        for (int e = 0; e < NEXP; e++) { g_count[e] = 0; g_psum[e] = 0.f; }
        g_zsum = 0.f;
    }
}

// ---------------- GEMM1: M_e = W1_e @ W2_e (3-stage smem + register pipeline) --------
// epilogue emits GEMM2 B-fragment tiles straight into g_MB
__global__ __launch_bounds__(256) void moe_gemm1() {
    constexpr int ITERS = DFFN / BKH;       // 32
    const int e  = blockIdx.z;
    const int m0 = blockIdx.x * BM;

    extern __shared__ __half smem[];
    __half* sA = smem;                       // 3 stages x SA_SZ
    __half* sB = smem + 3 * SA_SZ;           // 3 stages x SB_SZ

    const int tid = threadIdx.x, lane = tid & 31, warp = tid >> 5;

    const __half* aptr[4];
#pragma unroll
    for (int i = 0; i < 4; i++) {
        int rr = m0 + (tid >> 3) + i * 32;
        aptr[i] = g_W1h + (size_t)rr * (NEXP * DFFN) + (size_t)e * DFFN
                + (tid & 7) * 8;
    }
    const __half* Bt = g_W2B + (size_t)((e * 8 + blockIdx.y) * ITERS) * 8192;

    auto load_stage = [&](int it, int s) {
        __half* sAs = sA + s * SA_SZ;
        __half* sBs = sB + s * SB_SZ;
        int k0 = it * BKH;
#pragma unroll
        for (int i = 0; i < 4; i++)
            cpa16(sAs + ((tid >> 3) + i * 32) * SA_STRIDE + (tid & 7) * 8,
                  aptr[i] + k0);
        const __half* bsrc = Bt + (size_t)it * 8192;
#pragma unroll
        for (int p = 0; p < 4; p++)
            cpa16(sBs + p * 2048 + tid * 8, bsrc + p * 2048 + tid * 8);
        cpa_commit();
    };

    float acc[2][8][4];
#pragma unroll
    for (int a = 0; a < 2; a++)
#pragma unroll
        for (int b = 0; b < 8; b++)
#pragma unroll
            for (int c = 0; c < 4; c++) acc[a][b][c] = 0.f;

    const int wm  = (warp & 3) * 32;
    const int wng = (warp >> 2);

    uint32_t afr[2][2][4];
    uint4    bfr[2][4];

    auto load_frag = [&](int s, int ks, int buf) {
        const __half* sAs = sA + s * SA_SZ;
        const __half* sBs = sB + s * SB_SZ;
#pragma unroll
        for (int tm = 0; tm < 2; tm++) {
            const __half* p = sAs + (wm + tm * 16 + (lane & 15)) * SA_STRIDE
                            + ks * 16 + (lane >> 4) * 8;
            ldsm4(afr[buf][tm], p);
        }
        const __half* bq = sBs + ks * 2048 + wng * 1024 + lane * 8;
#pragma unroll
        for (int tp = 0; tp < 4; tp++)
            bfr[buf][tp] = *(const uint4*)(bq + tp * 256);
    };
    auto do_mma = [&](int buf) {
#pragma unroll
        for (int tm = 0; tm < 2; tm++)
#pragma unroll
            for (int tn = 0; tn < 8; tn++) {
                const uint32_t* bb = (tn & 1) ? &bfr[buf][tn >> 1].z
                                              : &bfr[buf][tn >> 1].x;
                mma16(acc[tm][tn], afr[buf][tm], bb);
            }
    };

    load_stage(0, 0);
    load_stage(1, 1);
    cpa_wait<1>();
    __syncthreads();
    load_frag(0, 0, 0);

#pragma unroll 1
    for (int it = 0; it < ITERS; ++it) {
        const int cur = it % 3;
#pragma unroll
        for (int ks = 0; ks < 4; ks++) {
            const int buf = ks & 1;
            if (ks == 0 && it + 2 < ITERS)
                load_stage(it + 2, (it + 2) % 3);
            if (ks < 3) {
                load_frag(cur, ks + 1, buf ^ 1);
            } else if (it + 1 < ITERS) {
                if (it + 2 < ITERS) cpa_wait<1>(); else cpa_wait<0>();
                __syncthreads();
                load_frag((it + 1) % 3, 0, buf ^ 1);
            }
            do_mma(buf);
        }
    }

    // ---- epilogue: restage C through smem, emit GEMM2 B-fragment tiles ----
    __syncthreads();
    __half* sh = smem;                     // [128][136] halfs = 69632 B
#pragma unroll
    for (int tm = 0; tm < 2; tm++)
#pragma unroll
        for (int half = 0; half < 2; half++) {
            int r = wm + tm * 16 + (lane >> 2) + half * 8;
#pragma unroll
            for (int tn = 0; tn < 8; tn++) {
                int c = wng * 64 + tn * 8 + (lane & 3) * 2;
                __half2 h = __floats2half2_rn(acc[tm][tn][half * 2 + 0],
                                              acc[tm][tn][half * 2 + 1]);
                *(__half2*)(sh + r * 136 + c) = h;
            }
        }
    __syncthreads();
    const int slot = warp;
#pragma unroll
    for (int sub = 0; sub < 2; sub++) {
        int kt = blockIdx.x * 2 + sub;      // GEMM2 K-tile index (KT=16)
        __half* tile = g_MB + ((size_t)(e * 8 + blockIdx.y) * 16 + kt) * 8192;
#pragma unroll
        for (int j = 0; j < 4; j++) {
            int idx = slot * 4 + j;
            int ks = idx >> 3, tp = idx & 7;
            int kb = sub * 64 + ks * 16 + 2 * (lane & 3);
            int n  = tp * 16 + (lane >> 2);
            __half h[8];
            h[0] = sh[kb * 136 + n];       h[1] = sh[(kb + 1) * 136 + n];
            h[2] = sh[(kb + 8) * 136 + n]; h[3] = sh[(kb + 9) * 136 + n];
            h[4] = sh[kb * 136 + n + 8];       h[5] = sh[(kb + 1) * 136 + n + 8];
            h[6] = sh[(kb + 8) * 136 + n + 8]; h[7] = sh[(kb + 9) * 136 + n + 8];
            *(uint4*)(tile + ks * 2048 + tp * 256 + lane * 8) = *(uint4*)h;
        }
    }
}

// ---------------- GEMM2: out[tok] += wsel * (gather(x) @ M_e)  (2-stage, 2 CTA/SM) ---
__global__ __launch_bounds__(256, 2) void moe_gemm2(float* out) {
    constexpr int ITERS = DIM / BKH;        // 16
    const int e   = blockIdx.z;
    const int cnt = g_count[e];
    const int m0  = blockIdx.x * BM;
    if (m0 >= cnt) return;
    const int n0  = blockIdx.y * BN;

    extern __shared__ __half smem[];
    __half* sA = smem;                       // 2 stages x SA_SZ
    __half* sB = smem + 2 * SA_SZ;           // 2 stages x SB_SZ

    const int tid = threadIdx.x, lane = tid & 31, warp = tid >> 5;

    const __half* aptr[4];
#pragma unroll
    for (int i = 0; i < 4; i++) {
        int rr = m0 + (tid >> 3) + i * 32;
        if (rr >= cnt) rr = cnt - 1;
        int tok = g_list[e * NUM_T + rr];
        aptr[i] = g_Xh + (size_t)tok * DIM + (tid & 7) * 8;
    }
    const __half* Bt = g_MB + (size_t)((e * 8 + blockIdx.y) * ITERS) * 8192;

    auto load_stage = [&](int it, int s) {
        __half* sAs = sA + s * SA_SZ;
        __half* sBs = sB + s * SB_SZ;
        int k0 = it * BKH;
#pragma unroll
        for (int i = 0; i < 4; i++)
            cpa16(sAs + ((tid >> 3) + i * 32) * SA_STRIDE + (tid & 7) * 8,
                  aptr[i] + k0);
        const __half* bsrc = Bt + (size_t)it * 8192;
#pragma unroll
        for (int p = 0; p < 4; p++)
            cpa16(sBs + p * 2048 + tid * 8, bsrc + p * 2048 + tid * 8);
        cpa_commit();
    };

    float acc[2][8][4];
#pragma unroll
    for (int a = 0; a < 2; a++)
#pragma unroll
        for (int b = 0; b < 8; b++)
#pragma unroll
            for (int c = 0; c < 4; c++) acc[a][b][c] = 0.f;

    const int wm  = (warp & 3) * 32;
    const int wng = (warp >> 2);

    auto compute_stage = [&](int s) {
        const __half* sAs = sA + s * SA_SZ;
        const __half* sBs = sB + s * SB_SZ;
#pragma unroll
        for (int ks = 0; ks < 4; ks++) {
            uint32_t afr[2][4];
#pragma unroll
            for (int tm = 0; tm < 2; tm++) {
                const __half* p = sAs + (wm + tm * 16 + (lane & 15)) * SA_STRIDE
                                + ks * 16 + (lane >> 4) * 8;
                ldsm4(afr[tm], p);
            }
            uint4 bfr[4];
            const __half* bq = sBs + ks * 2048 + wng * 1024 + lane * 8;
#pragma unroll
            for (int tp = 0; tp < 4; tp++)
                bfr[tp] = *(const uint4*)(bq + tp * 256);
#pragma unroll
            for (int tm = 0; tm < 2; tm++)
#pragma unroll
                for (int tn = 0; tn < 8; tn++) {
                    const uint32_t* bb = (tn & 1) ? &bfr[tn >> 1].z : &bfr[tn >> 1].x;
                    mma16(acc[tm][tn], afr[tm], bb);
                }
        }
    };

    load_stage(0, 0);
    load_stage(1, 1);
    cpa_wait<1>();
    __syncthreads();
#pragma unroll 1
    for (int it = 0; it < ITERS; ++it) {
        compute_stage(it & 1);
        __syncthreads();
        if (it + 2 < ITERS) {
            load_stage(it + 2, it & 1);
            cpa_wait<1>();
            __syncthreads();
        } else if (it + 1 < ITERS) {
            cpa_wait<0>();
            __syncthreads();
        }
    }

    // ---- epilogue: weighted vector reduction into out ----
#pragma unroll
    for (int tm = 0; tm < 2; tm++) {
#pragma unroll
        for (int half = 0; half < 2; half++) {
            int r  = wm + tm * 16 + (lane >> 2) + half * 8;
            int gr = m0 + r;
            if (gr < cnt) {
                float w   = g_wsel[e * NUM_T + gr];
                int   tok = g_list[e * NUM_T + gr];
                float* orow = out + (size_t)tok * DIM + n0 + wng * 64;
#pragma unroll
                for (int tn = 0; tn < 8; tn++) {
                    int c = tn * 8 + (lane & 3) * 2;
                    red2(orow + c,
                         w * acc[tm][tn][half * 2 + 0],
                         w * acc[tm][tn][half * 2 + 1]);
                }
            }
        }
    }
}

// ---------------- launch ----------------
extern "C" void kernel_launch(void* const* d_in, const int* in_sizes, int n_in,
                              void* d_out, int out_size) {
    const float* x  = (const float*)d_in[0];
    const float* wr = (const float*)d_in[1];
    const float* w1 = (const float*)d_in[2];
    const float* w2 = (const float*)d_in[3];
    float* out = (float*)d_out;

    cudaFuncSetAttribute(moe_gemm1,
                         cudaFuncAttributeMaxDynamicSharedMemorySize, SMEM1_BYTES);
    cudaFuncSetAttribute(moe_gemm2,
                         cudaFuncAttributeMaxDynamicSharedMemorySize, SMEM2_BYTES);

    // order: front(1) frag(2) gemm1(3) gemm2(4 <- ncu) finalize(5)
    front_kernel<<<RT_BLOCKS + CV_BLOCKS, 256>>>(
        (const float4*)x, (const float4*)w1, x, wr, out);
    frag_pack_w2<<<NEXP * 8 * (DFFN / 64), 256>>>(w2);
    moe_gemm1<<<dim3(DIM / BM, DIM / BN, NEXP), 256, SMEM1_BYTES>>>();
    moe_gemm2<<<dim3(NUM_T / BM, DIM / BN, NEXP), 256, SMEM2_BYTES>>>(out);
    finalize_kernel<<<1, 32>>>(out + OUT_MAT);
}

// round 16
// speedup vs baseline: 1.1778x; 1.0199x over previous
#include <cuda_runtime.h>
#include <cuda_fp16.h>
#include <cstdint>

#define NUM_T 8192
#define DIM   1024
#define NEXP  8
#define DFFN  2048
#define OUT_MAT (NUM_T * DIM)

#define BM 128
#define BN 128
#define BKH 64                          // K elements (halfs) per stage
#define SA_STRIDE 72                    // halfs, conflict-free ldmatrix
#define SA_SZ (BM * SA_STRIDE)          // 9216 halfs = 18 KB
#define SB_SZ 8192                      // halfs = 16 KB (frag tile)
#define SMEM1_BYTES (3 * (SA_SZ + SB_SZ) * 2)   // 104448 B (GEMM1: 3 stages)
#define SMEM2_BYTES (2 * (SA_SZ + SB_SZ) * 2)   //  69632 B (GEMM2: 2 stages)

#define RT_BLOCKS 512                   // router blocks (scheduled first)
#define CV_BLOCKS 24576                 // convert blocks
#define FP_BLOCKS 2048                  // frag-pack blocks (NEXP*8*(DFFN/64))

// ---------------- scratch (device globals; zero-initialized; no allocs) -------------
__device__ __half g_Xh [NUM_T * DIM];             // 16 MB fp16 x (row-major)
__device__ __half g_W1h[DIM * NEXP * DFFN];       // 32 MB fp16 w1 (row-major)
__device__ __half g_W2B[NEXP * 8 * 32 * 8192];    // 32 MB w2 fragment tiles (GEMM1 B)
__device__ __half g_MB [NEXP * 8 * 16 * 8192];    // 16 MB M fragment tiles (GEMM2 B)
__device__ int    g_list[NEXP * NUM_T];
__device__ float  g_wsel[NEXP * NUM_T];
__device__ int    g_count[NEXP];                  // zero-init; finalize re-zeroes
__device__ float  g_psum[NEXP];                   // zero-init; finalize re-zeroes
__device__ float  g_zsum;                         // zero-init; finalize re-zeroes

// ---------------- small helpers ----------------
__device__ __forceinline__ unsigned cvta_s(const void* p) {
    return (unsigned)__cvta_generic_to_shared((void*)p);
}
__device__ __forceinline__ void cpa16(void* sdst, const void* gsrc) {
    asm volatile("cp.async.cg.shared.global [%0], [%1], 16;"
                 :: "r"(cvta_s(sdst)), "l"(gsrc));
}
__device__ __forceinline__ void cpa_commit() {
    asm volatile("cp.async.commit_group;");
}
template<int N> __device__ __forceinline__ void cpa_wait() {
    asm volatile("cp.async.wait_group %0;" :: "n"(N));
}
__device__ __forceinline__ void ldsm4(uint32_t* a, const void* p) {
    asm volatile("ldmatrix.sync.aligned.m8n8.x4.shared.b16 {%0,%1,%2,%3}, [%4];"
                 : "=r"(a[0]), "=r"(a[1]), "=r"(a[2]), "=r"(a[3])
                 : "r"(cvta_s(p)));
}
__device__ __forceinline__ void mma16(float* c, const uint32_t* a, const uint32_t* b) {
    asm volatile("mma.sync.aligned.m16n8k16.row.col.f32.f16.f16.f32 "
                 "{%0,%1,%2,%3}, {%4,%5,%6,%7}, {%8,%9}, {%0,%1,%2,%3};"
                 : "+f"(c[0]), "+f"(c[1]), "+f"(c[2]), "+f"(c[3])
                 : "r"(a[0]), "r"(a[1]), "r"(a[2]), "r"(a[3]),
                   "r"(b[0]), "r"(b[1]));
}
__device__ __forceinline__ void red2(float* p, float a, float b) {
    asm volatile("red.global.v2.f32.add [%0], {%1, %2};"
                 :: "l"(p), "f"(a), "f"(b) : "memory");
}

// ---------------- fused front kernel --------------------------------------------------
// blocks [0, RT)            : router (2 tokens/warp) + zero out-slice
// blocks [RT, RT+CV)        : fp16 convert of x and w1
// blocks [RT+CV, RT+CV+FP)  : w2 fragment packing (independent of the other two)
__global__ __launch_bounds__(256) void front_kernel(
        const float4* __restrict__ x4, const float4* __restrict__ w14,
        const float*  __restrict__ x,  const float*  __restrict__ wr,
        const float*  __restrict__ w2, float* __restrict__ out) {
    __shared__ char sbuf[NEXP * DIM * 4];   // 32 KB: router swr OR frag staging
    __shared__ float s_p[NEXP];
    __shared__ float s_z;

    int tid = threadIdx.x;

    if (blockIdx.x >= RT_BLOCKS + CV_BLOCKS) {
        // ---- frag-pack path: w2 -> GEMM1 B fragment tiles ----
        __half (*sh)[136] = (__half(*)[136])sbuf;      // 64 x 136 halfs = 17408 B
        constexpr int KT = DFFN / 64;
        int b  = blockIdx.x - (RT_BLOCKS + CV_BLOCKS);
        int kt = b % KT;
        int nt = (b / KT) & 7;
        int e  = b / (KT * 8);
        int lane = tid & 31, slot = tid >> 5;

        const float* se = w2 + (size_t)e * DFFN * DIM + (size_t)(kt * 64) * DIM
                        + nt * 128;
#pragma unroll
        for (int i = tid; i < 2048; i += 256) {      // 2048 float4
            int r = i >> 5, c4 = i & 31;
            float4 v = *(const float4*)(se + (size_t)r * DIM + c4 * 4);
            __half2 h0 = __floats2half2_rn(v.x, v.y);
            __half2 h1 = __floats2half2_rn(v.z, v.w);
            uint2 o; o.x = *(uint32_t*)&h0; o.y = *(uint32_t*)&h1;
            *(uint2*)&sh[r][c4 * 4] = o;
        }
        __syncthreads();

        __half* tile = g_W2B + (size_t)b * 8192;
#pragma unroll
        for (int j = 0; j < 4; j++) {
            int idx = slot * 4 + j;           // 0..31 -> (ks, tp)
            int ks = idx >> 3, tp = idx & 7;
            int kb = ks * 16 + 2 * (lane & 3);
            int n  = tp * 16 + (lane >> 2);
            __half h[8];
            h[0] = sh[kb][n];     h[1] = sh[kb + 1][n];
            h[2] = sh[kb + 8][n]; h[3] = sh[kb + 9][n];
            h[4] = sh[kb][n + 8];     h[5] = sh[kb + 1][n + 8];
            h[6] = sh[kb + 8][n + 8]; h[7] = sh[kb + 9][n + 8];
            *(uint4*)(tile + ks * 2048 + tp * 256 + lane * 8) = *(uint4*)h;
        }
        return;
    }

    if (blockIdx.x >= RT_BLOCKS) {
        // ---- convert path: fp16-round x and w1 into scratch ----
        const unsigned NX = (NUM_T * DIM) / 4;          // 2097152
        unsigned i = (blockIdx.x - RT_BLOCKS) * 256u + tid;
        float4 v; __half* dst;
        if (i < NX) { v = x4[i];       dst = g_Xh  + (size_t)i * 4; }
        else        { v = w14[i - NX]; dst = g_W1h + (size_t)(i - NX) * 4; }
        __half2 h0 = __floats2half2_rn(v.x, v.y);
        __half2 h1 = __floats2half2_rn(v.z, v.w);
        uint2 o;
        o.x = *(uint32_t*)&h0;
        o.y = *(uint32_t*)&h1;
        *(uint2*)dst = o;
        return;
    }

    // ---- router path (2 tokens per warp); also zeroes this block's out slice ----
    float (*swr)[DIM] = (float(*)[DIM])sbuf;
    int rblk = blockIdx.x;                              // 0..511
    {
        float4 z4 = make_float4(0.f, 0.f, 0.f, 0.f);
        float4* ob = (float4*)out + (size_t)rblk * 4096;
#pragma unroll
        for (int i = tid; i < 4096; i += 256) ob[i] = z4;
    }

    for (int i = tid; i < NEXP * DIM; i += 256) {
        int d = i >> 3, e = i & 7;
        swr[e][d] = wr[i];
    }
    if (tid < NEXP) s_p[tid] = 0.f;
    if (tid == 0)   s_z = 0.f;
    __syncthreads();

    int lane = tid & 31, warp = tid >> 5;
    int t0 = rblk * 16 + warp * 2;                      // 2 tokens per warp

    float acc[2][NEXP];
#pragma unroll
    for (int tt = 0; tt < 2; tt++)
#pragma unroll
        for (int e = 0; e < NEXP; e++) acc[tt][e] = 0.f;

    const float4* xr0 = (const float4*)(x + (size_t)t0 * DIM);
    const float4* xr1 = (const float4*)(x + (size_t)(t0 + 1) * DIM);

    for (int c = lane; c < DIM / 4; c += 32) {
        float4 xv0 = xr0[c], xv1 = xr1[c];
#pragma unroll
        for (int e = 0; e < NEXP; e++) {
            float4 wv = *(const float4*)&swr[e][c * 4];
            acc[0][e] += xv0.x * wv.x + xv0.y * wv.y + xv0.z * wv.z + xv0.w * wv.w;
            acc[1][e] += xv1.x * wv.x + xv1.y * wv.y + xv1.z * wv.z + xv1.w * wv.w;
        }
    }
#pragma unroll
    for (int tt = 0; tt < 2; tt++)
#pragma unroll
        for (int e = 0; e < NEXP; e++)
            for (int o = 16; o; o >>= 1)
                acc[tt][e] += __shfl_xor_sync(0xffffffffu, acc[tt][e], o);

    if (lane < 2) {                                     // lane tt owns token t0+tt
        int t = t0 + lane;
        float m = acc[lane][0];
#pragma unroll
        for (int e = 1; e < NEXP; e++) m = fmaxf(m, acc[lane][e]);
        float p[NEXP], se = 0.f;
#pragma unroll
        for (int e = 0; e < NEXP; e++) { p[e] = expf(acc[lane][e] - m); se += p[e]; }
        float inv = 1.f / se;
#pragma unroll
        for (int e = 0; e < NEXP; e++) p[e] *= inv;
        float lse = m + logf(se);

        int e0 = 0;
#pragma unroll
        for (int e = 1; e < NEXP; e++) if (p[e] > p[e0]) e0 = e;
        int e1 = (e0 == 0) ? 1 : 0;
#pragma unroll
        for (int e = 0; e < NEXP; e++) if (e != e0 && p[e] > p[e1]) e1 = e;

        float w0 = p[e0], w1v = p[e1], s = w0 + w1v;
        w0 /= s; w1v /= s;

        int pos = atomicAdd(&g_count[e0], 1);
        g_list[e0 * NUM_T + pos] = t;  g_wsel[e0 * NUM_T + pos] = w0;
        pos = atomicAdd(&g_count[e1], 1);
        g_list[e1 * NUM_T + pos] = t;  g_wsel[e1 * NUM_T + pos] = w1v;

        atomicAdd(&s_z, lse * lse);
#pragma unroll
        for (int e = 0; e < NEXP; e++) atomicAdd(&s_p[e], p[e]);
    }
    __syncthreads();
    if (tid < NEXP) atomicAdd(&g_psum[tid], s_p[tid]);
    if (tid == 0)   atomicAdd(&g_zsum, s_z);
}

// ---------------- aux-loss outputs + state reset for next replay ----------------
__global__ void finalize_kernel(float* out_tail) {
    if (threadIdx.x == 0) {
        float z = g_zsum / (float)NUM_T;
        float lb = 0.f;
#pragma unroll
        for (int e = 0; e < NEXP; e++) {
            float f = (float)g_count[e] / (float)(NUM_T * 2);
            lb += f * (g_psum[e] / (float)NUM_T);
        }
        lb *= (float)NEXP;
        out_tail[0] = z;
        out_tail[1] = lb;
#pragma unroll
        for (int e = 0; e < NEXP; e++)
            out_tail[2 + e] = (float)g_count[e] / (float)(NUM_T * 2);
        // reset accumulators so the next graph replay starts from zero
#pragma unroll
        for (int e = 0; e < NEXP; e++) { g_count[e] = 0; g_psum[e] = 0.f; }
        g_zsum = 0.f;
    }
}

// ---------------- GEMM1: M_e = W1_e @ W2_e (3-stage smem + register pipeline) --------
// epilogue emits GEMM2 B-fragment tiles straight into g_MB
__global__ __launch_bounds__(256) void moe_gemm1() {
    constexpr int ITERS = DFFN / BKH;       // 32
    const int e  = blockIdx.z;
    const int m0 = blockIdx.x * BM;

    extern __shared__ __half smem[];
    __half* sA = smem;                       // 3 stages x SA_SZ
    __half* sB = smem + 3 * SA_SZ;           // 3 stages x SB_SZ

    const int tid = threadIdx.x, lane = tid & 31, warp = tid >> 5;

    const __half* aptr[4];
#pragma unroll
    for (int i = 0; i < 4; i++) {
        int rr = m0 + (tid >> 3) + i * 32;
        aptr[i] = g_W1h + (size_t)rr * (NEXP * DFFN) + (size_t)e * DFFN
                + (tid & 7) * 8;
    }
    const __half* Bt = g_W2B + (size_t)((e * 8 + blockIdx.y) * ITERS) * 8192;

    auto load_stage = [&](int it, int s) {
        __half* sAs = sA + s * SA_SZ;
        __half* sBs = sB + s * SB_SZ;
        int k0 = it * BKH;
#pragma unroll
        for (int i = 0; i < 4; i++)
            cpa16(sAs + ((tid >> 3) + i * 32) * SA_STRIDE + (tid & 7) * 8,
                  aptr[i] + k0);
        const __half* bsrc = Bt + (size_t)it * 8192;
#pragma unroll
        for (int p = 0; p < 4; p++)
            cpa16(sBs + p * 2048 + tid * 8, bsrc + p * 2048 + tid * 8);
        cpa_commit();
    };

    float acc[2][8][4];
#pragma unroll
    for (int a = 0; a < 2; a++)
#pragma unroll
        for (int b = 0; b < 8; b++)
#pragma unroll
            for (int c = 0; c < 4; c++) acc[a][b][c] = 0.f;

    const int wm  = (warp & 3) * 32;
    const int wng = (warp >> 2);

    uint32_t afr[2][2][4];
    uint4    bfr[2][4];

    auto load_frag = [&](int s, int ks, int buf) {
        const __half* sAs = sA + s * SA_SZ;
        const __half* sBs = sB + s * SB_SZ;
#pragma unroll
        for (int tm = 0; tm < 2; tm++) {
            const __half* p = sAs + (wm + tm * 16 + (lane & 15)) * SA_STRIDE
                            + ks * 16 + (lane >> 4) * 8;
            ldsm4(afr[buf][tm], p);
        }
        const __half* bq = sBs + ks * 2048 + wng * 1024 + lane * 8;
#pragma unroll
        for (int tp = 0; tp < 4; tp++)
            bfr[buf][tp] = *(const uint4*)(bq + tp * 256);
    };
    auto do_mma = [&](int buf) {
#pragma unroll
        for (int tm = 0; tm < 2; tm++)
#pragma unroll
            for (int tn = 0; tn < 8; tn++) {
                const uint32_t* bb = (tn & 1) ? &bfr[buf][tn >> 1].z
                                              : &bfr[buf][tn >> 1].x;
                mma16(acc[tm][tn], afr[buf][tm], bb);
            }
    };

    load_stage(0, 0);
    load_stage(1, 1);
    cpa_wait<1>();
    __syncthreads();
    load_frag(0, 0, 0);

#pragma unroll 1
    for (int it = 0; it < ITERS; ++it) {
        const int cur = it % 3;
#pragma unroll
        for (int ks = 0; ks < 4; ks++) {
            const int buf = ks & 1;
            if (ks == 0 && it + 2 < ITERS)
                load_stage(it + 2, (it + 2) % 3);
            if (ks < 3) {
                load_frag(cur, ks + 1, buf ^ 1);
            } else if (it + 1 < ITERS) {
                if (it + 2 < ITERS) cpa_wait<1>(); else cpa_wait<0>();
                __syncthreads();
                load_frag((it + 1) % 3, 0, buf ^ 1);
            }
            do_mma(buf);
        }
    }

    // ---- epilogue: restage C through smem, emit GEMM2 B-fragment tiles ----
    __syncthreads();
    __half* sh = smem;                     // [128][136] halfs = 69632 B
#pragma unroll
    for (int tm = 0; tm < 2; tm++)
#pragma unroll
        for (int half = 0; half < 2; half++) {
            int r = wm + tm * 16 + (lane >> 2) + half * 8;
#pragma unroll
            for (int tn = 0; tn < 8; tn++) {
                int c = wng * 64 + tn * 8 + (lane & 3) * 2;
                __half2 h = __floats2half2_rn(acc[tm][tn][half * 2 + 0],
                                              acc[tm][tn][half * 2 + 1]);
                *(__half2*)(sh + r * 136 + c) = h;
            }
        }
    __syncthreads();
    const int slot = warp;
#pragma unroll
    for (int sub = 0; sub < 2; sub++) {
        int kt = blockIdx.x * 2 + sub;      // GEMM2 K-tile index (KT=16)
        __half* tile = g_MB + ((size_t)(e * 8 + blockIdx.y) * 16 + kt) * 8192;
#pragma unroll
        for (int j = 0; j < 4; j++) {
            int idx = slot * 4 + j;
            int ks = idx >> 3, tp = idx & 7;
            int kb = sub * 64 + ks * 16 + 2 * (lane & 3);
            int n  = tp * 16 + (lane >> 2);
            __half h[8];
            h[0] = sh[kb * 136 + n];       h[1] = sh[(kb + 1) * 136 + n];
            h[2] = sh[(kb + 8) * 136 + n]; h[3] = sh[(kb + 9) * 136 + n];
            h[4] = sh[kb * 136 + n + 8];       h[5] = sh[(kb + 1) * 136 + n + 8];
            h[6] = sh[(kb + 8) * 136 + n + 8]; h[7] = sh[(kb + 9) * 136 + n + 8];
            *(uint4*)(tile + ks * 2048 + tp * 256 + lane * 8) = *(uint4*)h;
        }
    }
}

// ---------------- GEMM2: out[tok] += wsel * (gather(x) @ M_e)  (2-stage, 2 CTA/SM) ---
__global__ __launch_bounds__(256, 2) void moe_gemm2(float* out) {
    constexpr int ITERS = DIM / BKH;        // 16
    const int e   = blockIdx.z;
    const int cnt = g_count[e];
    const int m0  = blockIdx.x * BM;
    if (m0 >= cnt) return;
    const int n0  = blockIdx.y * BN;

    extern __shared__ __half smem[];
    __half* sA = smem;                       // 2 stages x SA_SZ
    __half* sB = smem + 2 * SA_SZ;           // 2 stages x SB_SZ

    const int tid = threadIdx.x, lane = tid & 31, warp = tid >> 5;

    const __half* aptr[4];
#pragma unroll
    for (int i = 0; i < 4; i++) {
        int rr = m0 + (tid >> 3) + i * 32;
        if (rr >= cnt) rr = cnt - 1;
        int tok = g_list[e * NUM_T + rr];
        aptr[i] = g_Xh + (size_t)tok * DIM + (tid & 7) * 8;
    }
    const __half* Bt = g_MB + (size_t)((e * 8 + blockIdx.y) * ITERS) * 8192;

    auto load_stage = [&](int it, int s) {
        __half* sAs = sA + s * SA_SZ;
        __half* sBs = sB + s * SB_SZ;
        int k0 = it * BKH;
#pragma unroll
        for (int i = 0; i < 4; i++)
            cpa16(sAs + ((tid >> 3) + i * 32) * SA_STRIDE + (tid & 7) * 8,
                  aptr[i] + k0);
        const __half* bsrc = Bt + (size_t)it * 8192;
#pragma unroll
        for (int p = 0; p < 4; p++)
            cpa16(sBs + p * 2048 + tid * 8, bsrc + p * 2048 + tid * 8);
        cpa_commit();
    };

    float acc[2][8][4];
#pragma unroll
    for (int a = 0; a < 2; a++)
#pragma unroll
        for (int b = 0; b < 8; b++)
#pragma unroll
            for (int c = 0; c < 4; c++) acc[a][b][c] = 0.f;

    const int wm  = (warp & 3) * 32;
    const int wng = (warp >> 2);

    auto compute_stage = [&](int s) {
        const __half* sAs = sA + s * SA_SZ;
        const __half* sBs = sB + s * SB_SZ;
#pragma unroll
        for (int ks = 0; ks < 4; ks++) {
            uint32_t afr[2][4];
#pragma unroll
            for (int tm = 0; tm < 2; tm++) {
                const __half* p = sAs + (wm + tm * 16 + (lane & 15)) * SA_STRIDE
                                + ks * 16 + (lane >> 4) * 8;
                ldsm4(afr[tm], p);
            }
            uint4 bfr[4];
            const __half* bq = sBs + ks * 2048 + wng * 1024 + lane * 8;
#pragma unroll
            for (int tp = 0; tp < 4; tp++)
                bfr[tp] = *(const uint4*)(bq + tp * 256);
#pragma unroll
            for (int tm = 0; tm < 2; tm++)
#pragma unroll
                for (int tn = 0; tn < 8; tn++) {
                    const uint32_t* bb = (tn & 1) ? &bfr[tn >> 1].z : &bfr[tn >> 1].x;
                    mma16(acc[tm][tn], afr[tm], bb);
                }
        }
    };

    load_stage(0, 0);
    load_stage(1, 1);
    cpa_wait<1>();
    __syncthreads();
#pragma unroll 1
    for (int it = 0; it < ITERS; ++it) {
        compute_stage(it & 1);
        __syncthreads();
        if (it + 2 < ITERS) {
            load_stage(it + 2, it & 1);
            cpa_wait<1>();
            __syncthreads();
        } else if (it + 1 < ITERS) {
            cpa_wait<0>();
            __syncthreads();
        }
    }

    // ---- epilogue: weighted vector reduction into out ----
#pragma unroll
    for (int tm = 0; tm < 2; tm++) {
#pragma unroll
        for (int half = 0; half < 2; half++) {
            int r  = wm + tm * 16 + (lane >> 2) + half * 8;
            int gr = m0 + r;
            if (gr < cnt) {
                float w   = g_wsel[e * NUM_T + gr];
                int   tok = g_list[e * NUM_T + gr];
                float* orow = out + (size_t)tok * DIM + n0 + wng * 64;
#pragma unroll
                for (int tn = 0; tn < 8; tn++) {
                    int c = tn * 8 + (lane & 3) * 2;
                    red2(orow + c,
                         w * acc[tm][tn][half * 2 + 0],
                         w * acc[tm][tn][half * 2 + 1]);
                }
            }
        }
    }
}

// ---------------- launch ----------------
extern "C" void kernel_launch(void* const* d_in, const int* in_sizes, int n_in,
                              void* d_out, int out_size) {
    const float* x  = (const float*)d_in[0];
    const float* wr = (const float*)d_in[1];
    const float* w1 = (const float*)d_in[2];
    const float* w2 = (const float*)d_in[3];
    float* out = (float*)d_out;

    cudaFuncSetAttribute(moe_gemm1,
                         cudaFuncAttributeMaxDynamicSharedMemorySize, SMEM1_BYTES);
    cudaFuncSetAttribute(moe_gemm2,
                         cudaFuncAttributeMaxDynamicSharedMemorySize, SMEM2_BYTES);

    // order: front(1) gemm1(2) gemm2(3) finalize(4)
    front_kernel<<<RT_BLOCKS + CV_BLOCKS + FP_BLOCKS, 256>>>(
        (const float4*)x, (const float4*)w1, x, wr, w2, out);
    moe_gemm1<<<dim3(DIM / BM, DIM / BN, NEXP), 256, SMEM1_BYTES>>>();
    moe_gemm2<<<dim3(NUM_T / BM, DIM / BN, NEXP), 256, SMEM2_BYTES>>>(out);
    finalize_kernel<<<1, 32>>>(out + OUT_MAT);
}